// round 13
// baseline (speedup 1.0000x reference)
#include <cuda_runtime.h>
#include <math.h>

#define B_   128
#define S_   512
#define IN_  128
#define H_   512
#define C_   1000
#define NWRP 16           // warps per rnn block
#define H2P  34           // per-row pitch of duplicated-h staging, in u64

// Scratch (device globals: allocation-free per harness rules)
__device__ float g_xp [(size_t)B_ * S_ * H_];   // input projection (both layers)
__device__ float g_seq[(size_t)B_ * S_ * H_];   // layer-0 hidden sequence
__device__ float g_h  [2 * B_ * H_];            // double-buffered hidden state
__device__ unsigned g_flags[128];               // per-block step flags (monotonic)

// ---------------- packed fp32x2 helpers (SASS FFMA2 path) -------------------
__device__ __forceinline__ unsigned long long pack2(float lo, float hi) {
    unsigned long long d;
    asm("mov.b64 %0, {%1, %2};" : "=l"(d)
        : "r"(__float_as_uint(lo)), "r"(__float_as_uint(hi)));
    return d;
}
__device__ __forceinline__ unsigned long long ffma2(
    unsigned long long a, unsigned long long b, unsigned long long c) {
    unsigned long long d;
    asm("fma.rn.f32x2 %0, %1, %2, %3;" : "=l"(d) : "l"(a), "l"(b), "l"(c));
    return d;
}
__device__ __forceinline__ unsigned long long fadd2(
    unsigned long long a, unsigned long long b) {
    unsigned long long d;
    asm("add.rn.f32x2 %0, %1, %2;" : "=l"(d) : "l"(a), "l"(b));
    return d;
}

// ---------------------------------------------------------------------------
// Persistent RNN layer. Grid (8,16) = 128 blocks, 512 threads (16 warps).
// Block tile: 16 rows (m0=bx*16) x 32 cols (n0=by*32). Whh tile [512][32]
// resident in smem. Warp g consumes h k-slice [32g,32g+32) = output tile of
// block (bx, by=g): polls that ONE block's flag (acquire), stages its slice
// DUPLICATED as (h,h) u64 pairs (no packs in the MMA loop), runs a 4x4 f32x2
// microtile. Partials double-buffered -> ONE __syncthreads per step. End of
// step: warps 1..15 bar.arrive (non-blocking, sprint into t+1); warp 0
// bar.sync + single release atomic. Flags monotonic -> replay-safe.
// ---------------------------------------------------------------------------
__global__ void __launch_bounds__(512, 1) rnn_layer_kernel(
    const float* __restrict__ xp, const float* __restrict__ Wh,
    float* __restrict__ hA, float* __restrict__ hB,
    float* __restrict__ seqOut)
{
    extern __shared__ float sm[];
    float* Ws = sm;                                        // [512][32]   64 KB
    unsigned long long* Hs2 =
        reinterpret_cast<unsigned long long*>(sm + 512 * 32); // 16x[16][H2P] u64, 69.6 KB
    float* Pr0 = reinterpret_cast<float*>(Hs2 + NWRP * 16 * H2P); // [16][512] 32 KB
    float* Pr1 = Pr0 + NWRP * 512;                                // [16][512] 32 KB
    __shared__ unsigned s_base;

    const int tid  = threadIdx.x;
    const int bx   = blockIdx.x;
    const int by   = blockIdx.y;
    const int m0   = bx << 4;             // 8 m-groups  -> 128 rows
    const int n0   = by << 5;             // 16 n-groups -> 512 cols
    const int g    = tid >> 5;            // warp = K-group 0..15
    const int lane = tid & 31;
    const int r0   = (lane >> 3) << 2;    // rows r0..r0+3
    const int c0   = (lane & 7) << 2;     // cols c0..c0+3
    const int kbeg = g << 5;              // 32 k per warp
    const int fi   = (bx << 4) + by;      // own flag index
    const int pfi  = (bx << 4) + g;       // producer flag for this warp
    unsigned long long* HsW = Hs2 + g * (16 * H2P);

    if (tid == 0) {
        unsigned cur;   // own flag: race-free base (only we increment it)
        asm volatile("ld.acquire.gpu.u32 %0, [%1];" : "=r"(cur) : "l"(&g_flags[fi]));
        s_base = cur;
    }

    // Load Whh tile once: Ws[k][n], n in [n0, n0+32), k in [0,512)
    for (int i = tid; i < 32 * 128; i += 512) {
        int n  = i & 31;
        int k4 = i >> 5;
        float4 v = *reinterpret_cast<const float4*>(
            &Wh[(size_t)(n0 + n) * H_ + (k4 << 2)]);
        int k = k4 << 2;
        Ws[(k + 0) * 32 + n] = v.x;
        Ws[(k + 1) * 32 + n] = v.y;
        Ws[(k + 2) * 32 + n] = v.z;
        Ws[(k + 3) * 32 + n] = v.w;
    }
    __syncthreads();
    const unsigned base = s_base;

    // Epilogue: warp g owns output row m0+g, lane = column
    const int er = g;                     // 0..15
    const int ec = lane;                  // 0..31

    const float* xrow = xp + ((size_t)(m0 + er) * S_) * H_ + n0 + ec;
    float xv = __ldg(xrow);               // t = 0

    for (int t = 0; t < S_; ++t) {
        const float* hp = (t & 1) ? hA : hB;
        float*       hn = (t & 1) ? hB : hA;
        float*       Pr = (t & 1) ? Pr1 : Pr0;

        float s = 0.f;

        if (t > 0) {
            // Wait for THIS warp's single producer block (acquire).
            if (lane == 0) {
                unsigned cur;
                do {
                    asm volatile("ld.acquire.gpu.u32 %0, [%1];"
                                 : "=r"(cur) : "l"(&g_flags[pfi]));
                } while (cur - base < (unsigned)t);
            }
            __syncwarp();

            // Stage own k-slice DUPLICATED: 16 rows x 32 k as (h,h) u64 pairs
#pragma unroll
            for (int j = 0; j < 4; ++j) {
                int idx = lane + (j << 5);
                int r = idx >> 3, k4 = idx & 7;
                float4 v = __ldcg(reinterpret_cast<const float4*>(
                    &hp[(size_t)(m0 + r) * H_ + kbeg + (k4 << 2)]));
                unsigned long long* dst = HsW + r * H2P + (k4 << 2);
                *reinterpret_cast<ulonglong2*>(dst) =
                    make_ulonglong2(pack2(v.x, v.x), pack2(v.y, v.y));
                *reinterpret_cast<ulonglong2*>(dst + 2) =
                    make_ulonglong2(pack2(v.z, v.z), pack2(v.w, v.w));
            }
            __syncwarp();

            unsigned long long a00 = 0, a01 = 0, a10 = 0, a11 = 0;
            unsigned long long a20 = 0, a21 = 0, a30 = 0, a31 = 0;

#pragma unroll
            for (int k4i = 0; k4i < 8; ++k4i) {
                const int kk = k4i << 2;
                // duplicated h: 2 ulonglong2 per row = pairs (k..k+3)
                ulonglong2 hA0 = *reinterpret_cast<const ulonglong2*>(&HsW[(r0 + 0) * H2P + kk]);
                ulonglong2 hB0 = *reinterpret_cast<const ulonglong2*>(&HsW[(r0 + 0) * H2P + kk + 2]);
                ulonglong2 hA1 = *reinterpret_cast<const ulonglong2*>(&HsW[(r0 + 1) * H2P + kk]);
                ulonglong2 hB1 = *reinterpret_cast<const ulonglong2*>(&HsW[(r0 + 1) * H2P + kk + 2]);
                ulonglong2 hA2 = *reinterpret_cast<const ulonglong2*>(&HsW[(r0 + 2) * H2P + kk]);
                ulonglong2 hB2 = *reinterpret_cast<const ulonglong2*>(&HsW[(r0 + 2) * H2P + kk + 2]);
                ulonglong2 hA3 = *reinterpret_cast<const ulonglong2*>(&HsW[(r0 + 3) * H2P + kk]);
                ulonglong2 hB3 = *reinterpret_cast<const ulonglong2*>(&HsW[(r0 + 3) * H2P + kk + 2]);
                const ulonglong2 w0 = *reinterpret_cast<const ulonglong2*>(&Ws[(kbeg + kk + 0) * 32 + c0]);
                const ulonglong2 w1 = *reinterpret_cast<const ulonglong2*>(&Ws[(kbeg + kk + 1) * 32 + c0]);
                const ulonglong2 w2 = *reinterpret_cast<const ulonglong2*>(&Ws[(kbeg + kk + 2) * 32 + c0]);
                const ulonglong2 w3 = *reinterpret_cast<const ulonglong2*>(&Ws[(kbeg + kk + 3) * 32 + c0]);
                a00 = ffma2(hA0.x, w0.x, a00); a01 = ffma2(hA0.x, w0.y, a01);
                a10 = ffma2(hA1.x, w0.x, a10); a11 = ffma2(hA1.x, w0.y, a11);
                a20 = ffma2(hA2.x, w0.x, a20); a21 = ffma2(hA2.x, w0.y, a21);
                a30 = ffma2(hA3.x, w0.x, a30); a31 = ffma2(hA3.x, w0.y, a31);
                a00 = ffma2(hA0.y, w1.x, a00); a01 = ffma2(hA0.y, w1.y, a01);
                a10 = ffma2(hA1.y, w1.x, a10); a11 = ffma2(hA1.y, w1.y, a11);
                a20 = ffma2(hA2.y, w1.x, a20); a21 = ffma2(hA2.y, w1.y, a21);
                a30 = ffma2(hA3.y, w1.x, a30); a31 = ffma2(hA3.y, w1.y, a31);
                a00 = ffma2(hB0.x, w2.x, a00); a01 = ffma2(hB0.x, w2.y, a01);
                a10 = ffma2(hB1.x, w2.x, a10); a11 = ffma2(hB1.x, w2.y, a11);
                a20 = ffma2(hB2.x, w2.x, a20); a21 = ffma2(hB2.x, w2.y, a21);
                a30 = ffma2(hB3.x, w2.x, a30); a31 = ffma2(hB3.x, w2.y, a31);
                a00 = ffma2(hB0.y, w3.x, a00); a01 = ffma2(hB0.y, w3.y, a01);
                a10 = ffma2(hB1.y, w3.x, a10); a11 = ffma2(hB1.y, w3.y, a11);
                a20 = ffma2(hB2.y, w3.x, a20); a21 = ffma2(hB2.y, w3.y, a21);
                a30 = ffma2(hB3.y, w3.x, a30); a31 = ffma2(hB3.y, w3.y, a31);
            }

            // Partials: Pr[g][row*32 + col]
            float* pg = &Pr[g << 9];
            *reinterpret_cast<ulonglong2*>(&pg[(r0 + 0) * 32 + c0]) = make_ulonglong2(a00, a01);
            *reinterpret_cast<ulonglong2*>(&pg[(r0 + 1) * 32 + c0]) = make_ulonglong2(a10, a11);
            *reinterpret_cast<ulonglong2*>(&pg[(r0 + 2) * 32 + c0]) = make_ulonglong2(a20, a21);
            *reinterpret_cast<ulonglong2*>(&pg[(r0 + 3) * 32 + c0]) = make_ulonglong2(a30, a31);
            __syncthreads();      // the ONLY full-block barrier per step

            // 16-way reduction: thread tid sums Pr[gg][tid]
#pragma unroll
            for (int gg = 0; gg < 16; ++gg)
                s += Pr[(gg << 9) + tid];
        }
        // t == 0: h_{-1}=0 -> output = tanh(xp)

        float o = tanhf(s + xv);
        __stcg(&hn[(size_t)(m0 + er) * H_ + n0 + ec], o);

        if (t != S_ - 1) {
            // Split end-of-step barrier: warps 1..15 arrive and sprint ahead;
            // warp 0 waits for everyone (incl. own arrive) and releases.
            if (g != 0) {
                asm volatile("bar.arrive 1, 512;" ::: "memory");
            } else {
                asm volatile("bar.sync 1, 512;" ::: "memory");
                if (lane == 0)
                    asm volatile("red.release.gpu.global.add.u32 [%0], %1;"
                                 :: "l"(&g_flags[fi]), "r"(1u) : "memory");
            }
        }

        if (seqOut)
            __stcg(&seqOut[((size_t)(m0 + er) * S_ + t) * H_ + n0 + ec], o);

        if (t != S_ - 1)   // prefetch next xp (hides under the poll)
            xv = __ldg(xrow + (size_t)(t + 1) * H_);
    }
}

// ---------------------------------------------------------------------------
// C[M,N] = A[M,K] @ W[N,K]^T + b1[N] + b2[N]
// 128x64 tile, BK=16, 256 threads, 8x4 microtile, packed f32x2 FMAs,
// register double-buffering of the next K-tile to hide GMEM latency.
// ---------------------------------------------------------------------------
__global__ __launch_bounds__(256) void sgemm_bias(
    const float* __restrict__ A, const float* __restrict__ W,
    const float* __restrict__ b1, const float* __restrict__ b2,
    float* __restrict__ C, int M, int N, int K)
{
    __shared__ float As[16][132];
    __shared__ float Wt[16][68];
    const int tid = threadIdx.x;
    const int tx = tid & 15, ty = tid >> 4;
    const int m0 = blockIdx.x * 128, n0 = blockIdx.y * 64;

    const int a_lr = tid >> 2, a_lk = (tid & 3) << 2;       // A-stage indices
    const int w_ln = tid >> 2, w_lk = (tid & 3) << 2;       // W-stage indices
    const float* Ap0 = &A[(size_t)(m0 + a_lr) * K + a_lk];
    const float* Ap1 = &A[(size_t)(m0 + a_lr + 64) * K + a_lk];
    const float* Wp  = &W[(size_t)(n0 + w_ln) * K + w_lk];

    unsigned long long acc[8][2];
#pragma unroll
    for (int i = 0; i < 8; ++i) { acc[i][0] = 0; acc[i][1] = 0; }

    // Prologue: load first K-tile
    float4 av0 = *reinterpret_cast<const float4*>(Ap0);
    float4 av1 = *reinterpret_cast<const float4*>(Ap1);
    float4 wv  = *reinterpret_cast<const float4*>(Wp);

    for (int k0 = 0; k0 < K; k0 += 16) {
        // Stage current tile from registers
        As[a_lk + 0][a_lr] = av0.x; As[a_lk + 1][a_lr] = av0.y;
        As[a_lk + 2][a_lr] = av0.z; As[a_lk + 3][a_lr] = av0.w;
        As[a_lk + 0][a_lr + 64] = av1.x; As[a_lk + 1][a_lr + 64] = av1.y;
        As[a_lk + 2][a_lr + 64] = av1.z; As[a_lk + 3][a_lr + 64] = av1.w;
        Wt[w_lk + 0][w_ln] = wv.x; Wt[w_lk + 1][w_ln] = wv.y;
        Wt[w_lk + 2][w_ln] = wv.z; Wt[w_lk + 3][w_ln] = wv.w;
        __syncthreads();

        // Prefetch next tile (overlaps the MMA below)
        if (k0 + 16 < K) {
            av0 = *reinterpret_cast<const float4*>(Ap0 + k0 + 16);
            av1 = *reinterpret_cast<const float4*>(Ap1 + k0 + 16);
            wv  = *reinterpret_cast<const float4*>(Wp  + k0 + 16);
        }

#pragma unroll
        for (int kk = 0; kk < 16; ++kk) {
            float4 x0 = *reinterpret_cast<const float4*>(&As[kk][ty << 3]);
            float4 x1 = *reinterpret_cast<const float4*>(&As[kk][(ty << 3) + 4]);
            const ulonglong2 w = *reinterpret_cast<const ulonglong2*>(&Wt[kk][tx << 2]);
            unsigned long long d;
#define GEMM_ROW(i, av, C)                                                     \
            d = pack2(av.C, av.C);                                             \
            acc[i][0] = ffma2(d, w.x, acc[i][0]);                              \
            acc[i][1] = ffma2(d, w.y, acc[i][1]);
            GEMM_ROW(0, x0, x) GEMM_ROW(1, x0, y) GEMM_ROW(2, x0, z) GEMM_ROW(3, x0, w)
            GEMM_ROW(4, x1, x) GEMM_ROW(5, x1, y) GEMM_ROW(6, x1, z) GEMM_ROW(7, x1, w)
#undef GEMM_ROW
        }
        __syncthreads();
    }

    const int n = n0 + (tx << 2);
    unsigned long long bb0 = pack2(b1[n + 0] + b2[n + 0], b1[n + 1] + b2[n + 1]);
    unsigned long long bb1 = pack2(b1[n + 2] + b2[n + 2], b1[n + 3] + b2[n + 3]);
#pragma unroll
    for (int i = 0; i < 8; ++i) {
        int m = m0 + (ty << 3) + i;
        *reinterpret_cast<ulonglong2*>(&C[(size_t)m * N + n]) =
            make_ulonglong2(fadd2(acc[i][0], bb0), fadd2(acc[i][1], bb1));
    }
}

// ---------------------------------------------------------------------------
// logits = h_last @ W_out^T + b_out; out = log_softmax(logits)
// ---------------------------------------------------------------------------
__global__ __launch_bounds__(256) void out_kernel(
    const float* __restrict__ h, const float* __restrict__ Wout,
    const float* __restrict__ bout, float* __restrict__ out)
{
    __shared__ float hs[H_];
    __shared__ float logits[C_];
    __shared__ float red[8];
    int b = blockIdx.x;
    int tid = threadIdx.x;
    int warp = tid >> 5, lane = tid & 31;

    for (int k = tid; k < H_; k += 256) hs[k] = h[(size_t)b * H_ + k];
    __syncthreads();

    for (int c = warp; c < C_; c += 8) {
        const float* wr = Wout + (size_t)c * H_;
        float s = 0.f;
#pragma unroll
        for (int k = lane; k < H_; k += 32) s += hs[k] * wr[k];
#pragma unroll
        for (int off = 16; off > 0; off >>= 1) s += __shfl_down_sync(0xffffffffu, s, off);
        if (lane == 0) logits[c] = s + bout[c];
    }
    __syncthreads();

    float mx = -1e30f;
    for (int c = tid; c < C_; c += 256) mx = fmaxf(mx, logits[c]);
#pragma unroll
    for (int off = 16; off > 0; off >>= 1) mx = fmaxf(mx, __shfl_down_sync(0xffffffffu, mx, off));
    if (lane == 0) red[warp] = mx;
    __syncthreads();
    if (tid == 0) {
        float m2 = red[0];
        for (int i = 1; i < 8; i++) m2 = fmaxf(m2, red[i]);
        red[0] = m2;
    }
    __syncthreads();
    mx = red[0];
    __syncthreads();

    float se = 0.f;
    for (int c = tid; c < C_; c += 256) se += expf(logits[c] - mx);
#pragma unroll
    for (int off = 16; off > 0; off >>= 1) se += __shfl_down_sync(0xffffffffu, se, off);
    if (lane == 0) red[warp] = se;
    __syncthreads();
    if (tid == 0) {
        float s2 = 0.f;
        for (int i = 0; i < 8; i++) s2 += red[i];
        red[0] = logf(s2);
    }
    __syncthreads();
    float lse = red[0];

    for (int c = tid; c < C_; c += 256)
        out[(size_t)b * C_ + c] = logits[c] - mx - lse;
}

extern "C" void kernel_launch(void* const* d_in, const int* in_sizes, int n_in,
                              void* d_out, int out_size)
{
    (void)in_sizes; (void)n_in; (void)out_size;
    const float* x     = (const float*)d_in[0];
    const float* W_ih0 = (const float*)d_in[1];
    const float* W_hh0 = (const float*)d_in[2];
    const float* b_ih0 = (const float*)d_in[3];
    const float* b_hh0 = (const float*)d_in[4];
    const float* W_ih1 = (const float*)d_in[5];
    const float* W_hh1 = (const float*)d_in[6];
    const float* b_ih1 = (const float*)d_in[7];
    const float* b_hh1 = (const float*)d_in[8];
    const float* W_out = (const float*)d_in[9];
    const float* b_out = (const float*)d_in[10];
    float* out = (float*)d_out;

    float *xp, *seq, *hbuf;
    cudaGetSymbolAddress((void**)&xp,   g_xp);
    cudaGetSymbolAddress((void**)&seq,  g_seq);
    cudaGetSymbolAddress((void**)&hbuf, g_h);
    float* hA = hbuf;
    float* hB = hbuf + B_ * H_;

    const int smem_bytes =
        512 * 32 * 4 + NWRP * 16 * H2P * 8 + 2 * NWRP * 512 * 4;  // 200704
    cudaFuncSetAttribute(rnn_layer_kernel,
                         cudaFuncAttributeMaxDynamicSharedMemorySize, smem_bytes);

    dim3 gg(B_ * S_ / 128, H_ / 64);  // (512, 8)
    dim3 gr(B_ / 16, H_ / 32);        // (8, 16) = 128 persistent blocks

    // layer 0
    sgemm_bias<<<gg, 256>>>(x, W_ih0, b_ih0, b_hh0, xp, B_ * S_, H_, IN_);
    rnn_layer_kernel<<<gr, 512, smem_bytes>>>(xp, W_hh0, hA, hB, seq);

    // layer 1
    sgemm_bias<<<gg, 256>>>(seq, W_ih1, b_ih1, b_hh1, xp, B_ * S_, H_, H_);
    rnn_layer_kernel<<<gr, 512, smem_bytes>>>(xp, W_hh1, hA, hB, nullptr);

    // output head on h_{S-1} (t=511 odd -> final state in hB)
    out_kernel<<<B_, 256>>>(hB, W_out, b_out, out);
}

// round 14
// speedup vs baseline: 1.1433x; 1.1433x over previous
#include <cuda_runtime.h>
#include <math.h>

#define B_   128
#define S_   512
#define IN_  128
#define H_   512
#define C_   1000
#define NWRP 16           // warps per rnn block
#define HSPW 36           // per-warp Hs row pitch (floats), 16B-aligned

// Scratch (device globals: allocation-free per harness rules)
__device__ float g_xp [(size_t)B_ * S_ * H_];   // input projection (both layers)
__device__ float g_seq[(size_t)B_ * S_ * H_];   // layer-0 hidden sequence
__device__ float g_h  [2 * B_ * H_];            // double-buffered hidden state
__device__ unsigned g_flags[128];               // per-block step flags (monotonic)

// ---------------- packed fp32x2 helpers (SASS FFMA2 path) -------------------
__device__ __forceinline__ unsigned long long pack2(float lo, float hi) {
    unsigned long long d;
    asm("mov.b64 %0, {%1, %2};" : "=l"(d)
        : "r"(__float_as_uint(lo)), "r"(__float_as_uint(hi)));
    return d;
}
__device__ __forceinline__ unsigned long long ffma2(
    unsigned long long a, unsigned long long b, unsigned long long c) {
    unsigned long long d;
    asm("fma.rn.f32x2 %0, %1, %2, %3;" : "=l"(d) : "l"(a), "l"(b), "l"(c));
    return d;
}
__device__ __forceinline__ unsigned long long fadd2(
    unsigned long long a, unsigned long long b) {
    unsigned long long d;
    asm("add.rn.f32x2 %0, %1, %2;" : "=l"(d) : "l"(a), "l"(b));
    return d;
}
__device__ __forceinline__ float2 unpack2(unsigned long long v) {
    unsigned lo, hi;
    asm("mov.b64 {%0, %1}, %2;" : "=r"(lo), "=r"(hi) : "l"(v));
    return make_float2(__uint_as_float(lo), __uint_as_float(hi));
}

// ---------------------------------------------------------------------------
// Persistent RNN layer (R11 dataflow + warp-specialized epilogue overlap).
// Grid (8,16) = 128 blocks, 512 threads (16 warps). Block tile: 16 rows
// (m0=bx*16) x 32 cols (n0=by*32). Whh tile [512][32] resident in smem.
// Warp g consumes h k-slice [32g,32g+32) = output tile of block (bx, by=g):
// polls that ONE block's flag (acquire), stages its slice (warp-private,
// syncwarp only), runs a 4x4 f32x2 microtile, dumps packed partials into
// the DOUBLE-BUFFERED Pr. After the single __syncthreads, only warps 0-7
// (256 threads, 2 outputs each) reduce+tanh+store, bar.sync on named
// barrier 2 (256 threads), thread 0 releases. Warps 8-15 sprint directly
// into step t+1's poll/stage/MMA, overlapping the epilogue.
// Flags monotonic (+511/launch) -> replay-safe.
// ---------------------------------------------------------------------------
__global__ void __launch_bounds__(512, 1) rnn_layer_kernel(
    const float* __restrict__ xp, const float* __restrict__ Wh,
    float* __restrict__ hA, float* __restrict__ hB,
    float* __restrict__ seqOut)
{
    extern __shared__ float sm[];
    float* Ws  = sm;                       // [512][32] k-major        (64 KB)
    float* Hs  = Ws + 512 * 32;            // 16 x [16][HSPW] per-warp (36 KB)
    float* Pr0 = Hs + NWRP * 16 * HSPW;    // [16][512] partials buf 0 (32 KB)
    float* Pr1 = Pr0 + NWRP * 512;         // [16][512] partials buf 1 (32 KB)
    __shared__ unsigned s_base;

    const int tid  = threadIdx.x;
    const int bx   = blockIdx.x;
    const int by   = blockIdx.y;
    const int m0   = bx << 4;             // 8 m-groups  -> 128 rows
    const int n0   = by << 5;             // 16 n-groups -> 512 cols
    const int g    = tid >> 5;            // warp = K-group 0..15
    const int lane = tid & 31;
    const int r0   = (lane >> 3) << 2;    // rows r0..r0+3
    const int c0   = (lane & 7) << 2;     // cols c0..c0+3
    const int kbeg = g << 5;              // 32 k per warp
    const int fi   = (bx << 4) + by;      // own flag index
    const int pfi  = (bx << 4) + g;       // producer flag for this warp
    float* HsW = Hs + g * (16 * HSPW);

    if (tid == 0) {
        unsigned cur;   // own flag: race-free base (only we increment it)
        asm volatile("ld.acquire.gpu.u32 %0, [%1];" : "=r"(cur) : "l"(&g_flags[fi]));
        s_base = cur;
    }

    // Load Whh tile once: Ws[k][n], n in [n0, n0+32), k in [0,512)
    for (int i = tid; i < 32 * 128; i += 512) {
        int n  = i & 31;
        int k4 = i >> 5;
        float4 v = *reinterpret_cast<const float4*>(
            &Wh[(size_t)(n0 + n) * H_ + (k4 << 2)]);
        int k = k4 << 2;
        Ws[(k + 0) * 32 + n] = v.x;
        Ws[(k + 1) * 32 + n] = v.y;
        Ws[(k + 2) * 32 + n] = v.z;
        Ws[(k + 3) * 32 + n] = v.w;
    }
    __syncthreads();
    const unsigned base = s_base;

    // Epilogue role: threads 0..255 (warps 0-7), each owns 2 adjacent outputs
    const int eer = tid >> 4;             // 0..15 (rows, for tid<256)
    const int eec = (tid & 15) << 1;      // even 0..30
    const bool epi = (tid < 256);

    const float* xrow = xp + ((size_t)(m0 + eer) * S_) * H_ + n0 + eec;
    float2 xv = make_float2(0.f, 0.f);
    if (epi) xv = __ldg(reinterpret_cast<const float2*>(xrow));   // t = 0

    for (int t = 0; t < S_; ++t) {
        const float* hp = (t & 1) ? hA : hB;
        float*       hn = (t & 1) ? hB : hA;
        float*       Pr = (t & 1) ? Pr1 : Pr0;

        if (t > 0) {
            // Wait for THIS warp's single producer block (acquire).
            if (lane == 0) {
                unsigned cur;
                do {
                    asm volatile("ld.acquire.gpu.u32 %0, [%1];"
                                 : "=r"(cur) : "l"(&g_flags[pfi]));
                } while (cur - base < (unsigned)t);
            }
            __syncwarp();

            // Stage own k-slice: 16 rows x 32 k (warp-private region)
#pragma unroll
            for (int j = 0; j < 4; ++j) {
                int idx = lane + (j << 5);
                int r = idx >> 3, k4 = idx & 7;
                float4 v = __ldcg(reinterpret_cast<const float4*>(
                    &hp[(size_t)(m0 + r) * H_ + kbeg + (k4 << 2)]));
                *reinterpret_cast<float4*>(&HsW[r * HSPW + (k4 << 2)]) = v;
            }
            __syncwarp();

            unsigned long long a00 = 0, a01 = 0, a10 = 0, a11 = 0;
            unsigned long long a20 = 0, a21 = 0, a30 = 0, a31 = 0;

#pragma unroll
            for (int k4i = 0; k4i < 8; ++k4i) {
                const int kk = k4i << 2;
                float4 h0 = *reinterpret_cast<const float4*>(&HsW[(r0 + 0) * HSPW + kk]);
                float4 h1 = *reinterpret_cast<const float4*>(&HsW[(r0 + 1) * HSPW + kk]);
                float4 h2 = *reinterpret_cast<const float4*>(&HsW[(r0 + 2) * HSPW + kk]);
                float4 h3 = *reinterpret_cast<const float4*>(&HsW[(r0 + 3) * HSPW + kk]);
#define RNN_SUBK(ss, C)                                                        \
                {                                                              \
                    const ulonglong2 w = *reinterpret_cast<const ulonglong2*>( \
                        &Ws[(kbeg + kk + ss) * 32 + c0]);                      \
                    unsigned long long d;                                      \
                    d = pack2(h0.C, h0.C);                                     \
                    a00 = ffma2(d, w.x, a00); a01 = ffma2(d, w.y, a01);        \
                    d = pack2(h1.C, h1.C);                                     \
                    a10 = ffma2(d, w.x, a10); a11 = ffma2(d, w.y, a11);        \
                    d = pack2(h2.C, h2.C);                                     \
                    a20 = ffma2(d, w.x, a20); a21 = ffma2(d, w.y, a21);        \
                    d = pack2(h3.C, h3.C);                                     \
                    a30 = ffma2(d, w.x, a30); a31 = ffma2(d, w.y, a31);        \
                }
                RNN_SUBK(0, x)
                RNN_SUBK(1, y)
                RNN_SUBK(2, z)
                RNN_SUBK(3, w)
#undef RNN_SUBK
            }

            // Partials: Pr[g][row*32 + col]
            float* pg = &Pr[g << 9];
            *reinterpret_cast<ulonglong2*>(&pg[(r0 + 0) * 32 + c0]) = make_ulonglong2(a00, a01);
            *reinterpret_cast<ulonglong2*>(&pg[(r0 + 1) * 32 + c0]) = make_ulonglong2(a10, a11);
            *reinterpret_cast<ulonglong2*>(&pg[(r0 + 2) * 32 + c0]) = make_ulonglong2(a20, a21);
            *reinterpret_cast<ulonglong2*>(&pg[(r0 + 3) * 32 + c0]) = make_ulonglong2(a30, a31);
            __syncthreads();      // the ONLY full-block barrier per step
        }

        // ---- Epilogue: warps 0-7 only; warps 8-15 sprint to step t+1 ----
        if (epi) {
            unsigned long long sp = 0;
            if (t > 0) {
                const float* pb = Pr + eer * 32 + eec;
#pragma unroll
                for (int gg = 0; gg < 16; ++gg)
                    sp = fadd2(sp, *reinterpret_cast<const unsigned long long*>(
                                       pb + (gg << 9)));
            }
            float2 sf = unpack2(sp);       // (0,0) at t==0: h_{-1} = 0
            float2 o;
            o.x = tanhf(sf.x + xv.x);
            o.y = tanhf(sf.y + xv.y);
            __stcg(reinterpret_cast<float2*>(
                &hn[(size_t)(m0 + eer) * H_ + n0 + eec]), o);

            // All 256 epilogue threads' stores done -> release once.
            asm volatile("bar.sync 2, 256;" ::: "memory");
            if (tid == 0 && t != S_ - 1)
                asm volatile("red.release.gpu.global.add.u32 [%0], %1;"
                             :: "l"(&g_flags[fi]), "r"(1u) : "memory");

            if (seqOut)
                __stcg(reinterpret_cast<float2*>(
                    &seqOut[((size_t)(m0 + eer) * S_ + t) * H_ + n0 + eec]), o);

            if (t != S_ - 1)
                xv = __ldg(reinterpret_cast<const float2*>(
                    xrow + (size_t)(t + 1) * H_));
        }
    }
}

// ---------------------------------------------------------------------------
// C[M,N] = A[M,K] @ W[N,K]^T + b1[N] + b2[N]
// 128x64 tile, BK=16, 256 threads, 8x4 microtile, packed f32x2 FMAs,
// register double-buffering of the next K-tile to hide GMEM latency.
// ---------------------------------------------------------------------------
__global__ __launch_bounds__(256) void sgemm_bias(
    const float* __restrict__ A, const float* __restrict__ W,
    const float* __restrict__ b1, const float* __restrict__ b2,
    float* __restrict__ C, int M, int N, int K)
{
    __shared__ float As[16][132];
    __shared__ float Wt[16][68];
    const int tid = threadIdx.x;
    const int tx = tid & 15, ty = tid >> 4;
    const int m0 = blockIdx.x * 128, n0 = blockIdx.y * 64;

    const int a_lr = tid >> 2, a_lk = (tid & 3) << 2;
    const int w_ln = tid >> 2, w_lk = (tid & 3) << 2;
    const float* Ap0 = &A[(size_t)(m0 + a_lr) * K + a_lk];
    const float* Ap1 = &A[(size_t)(m0 + a_lr + 64) * K + a_lk];
    const float* Wp  = &W[(size_t)(n0 + w_ln) * K + w_lk];

    unsigned long long acc[8][2];
#pragma unroll
    for (int i = 0; i < 8; ++i) { acc[i][0] = 0; acc[i][1] = 0; }

    float4 av0 = *reinterpret_cast<const float4*>(Ap0);
    float4 av1 = *reinterpret_cast<const float4*>(Ap1);
    float4 wv  = *reinterpret_cast<const float4*>(Wp);

    for (int k0 = 0; k0 < K; k0 += 16) {
        As[a_lk + 0][a_lr] = av0.x; As[a_lk + 1][a_lr] = av0.y;
        As[a_lk + 2][a_lr] = av0.z; As[a_lk + 3][a_lr] = av0.w;
        As[a_lk + 0][a_lr + 64] = av1.x; As[a_lk + 1][a_lr + 64] = av1.y;
        As[a_lk + 2][a_lr + 64] = av1.z; As[a_lk + 3][a_lr + 64] = av1.w;
        Wt[w_lk + 0][w_ln] = wv.x; Wt[w_lk + 1][w_ln] = wv.y;
        Wt[w_lk + 2][w_ln] = wv.z; Wt[w_lk + 3][w_ln] = wv.w;
        __syncthreads();

        if (k0 + 16 < K) {
            av0 = *reinterpret_cast<const float4*>(Ap0 + k0 + 16);
            av1 = *reinterpret_cast<const float4*>(Ap1 + k0 + 16);
            wv  = *reinterpret_cast<const float4*>(Wp  + k0 + 16);
        }

#pragma unroll
        for (int kk = 0; kk < 16; ++kk) {
            float4 x0 = *reinterpret_cast<const float4*>(&As[kk][ty << 3]);
            float4 x1 = *reinterpret_cast<const float4*>(&As[kk][(ty << 3) + 4]);
            const ulonglong2 w = *reinterpret_cast<const ulonglong2*>(&Wt[kk][tx << 2]);
            unsigned long long d;
#define GEMM_ROW(i, av, C)                                                     \
            d = pack2(av.C, av.C);                                             \
            acc[i][0] = ffma2(d, w.x, acc[i][0]);                              \
            acc[i][1] = ffma2(d, w.y, acc[i][1]);
            GEMM_ROW(0, x0, x) GEMM_ROW(1, x0, y) GEMM_ROW(2, x0, z) GEMM_ROW(3, x0, w)
            GEMM_ROW(4, x1, x) GEMM_ROW(5, x1, y) GEMM_ROW(6, x1, z) GEMM_ROW(7, x1, w)
#undef GEMM_ROW
        }
        __syncthreads();
    }

    const int n = n0 + (tx << 2);
    unsigned long long bb0 = pack2(b1[n + 0] + b2[n + 0], b1[n + 1] + b2[n + 1]);
    unsigned long long bb1 = pack2(b1[n + 2] + b2[n + 2], b1[n + 3] + b2[n + 3]);
#pragma unroll
    for (int i = 0; i < 8; ++i) {
        int m = m0 + (ty << 3) + i;
        *reinterpret_cast<ulonglong2*>(&C[(size_t)m * N + n]) =
            make_ulonglong2(fadd2(acc[i][0], bb0), fadd2(acc[i][1], bb1));
    }
}

// ---------------------------------------------------------------------------
// logits = h_last @ W_out^T + b_out; out = log_softmax(logits)
// ---------------------------------------------------------------------------
__global__ __launch_bounds__(256) void out_kernel(
    const float* __restrict__ h, const float* __restrict__ Wout,
    const float* __restrict__ bout, float* __restrict__ out)
{
    __shared__ float hs[H_];
    __shared__ float logits[C_];
    __shared__ float red[8];
    int b = blockIdx.x;
    int tid = threadIdx.x;
    int warp = tid >> 5, lane = tid & 31;

    for (int k = tid; k < H_; k += 256) hs[k] = h[(size_t)b * H_ + k];
    __syncthreads();

    for (int c = warp; c < C_; c += 8) {
        const float* wr = Wout + (size_t)c * H_;
        float s = 0.f;
#pragma unroll
        for (int k = lane; k < H_; k += 32) s += hs[k] * wr[k];
#pragma unroll
        for (int off = 16; off > 0; off >>= 1) s += __shfl_down_sync(0xffffffffu, s, off);
        if (lane == 0) logits[c] = s + bout[c];
    }
    __syncthreads();

    float mx = -1e30f;
    for (int c = tid; c < C_; c += 256) mx = fmaxf(mx, logits[c]);
#pragma unroll
    for (int off = 16; off > 0; off >>= 1) mx = fmaxf(mx, __shfl_down_sync(0xffffffffu, mx, off));
    if (lane == 0) red[warp] = mx;
    __syncthreads();
    if (tid == 0) {
        float m2 = red[0];
        for (int i = 1; i < 8; i++) m2 = fmaxf(m2, red[i]);
        red[0] = m2;
    }
    __syncthreads();
    mx = red[0];
    __syncthreads();

    float se = 0.f;
    for (int c = tid; c < C_; c += 256) se += expf(logits[c] - mx);
#pragma unroll
    for (int off = 16; off > 0; off >>= 1) se += __shfl_down_sync(0xffffffffu, se, off);
    if (lane == 0) red[warp] = se;
    __syncthreads();
    if (tid == 0) {
        float s2 = 0.f;
        for (int i = 0; i < 8; i++) s2 += red[i];
        red[0] = logf(s2);
    }
    __syncthreads();
    float lse = red[0];

    for (int c = tid; c < C_; c += 256)
        out[(size_t)b * C_ + c] = logits[c] - mx - lse;
}

extern "C" void kernel_launch(void* const* d_in, const int* in_sizes, int n_in,
                              void* d_out, int out_size)
{
    (void)in_sizes; (void)n_in; (void)out_size;
    const float* x     = (const float*)d_in[0];
    const float* W_ih0 = (const float*)d_in[1];
    const float* W_hh0 = (const float*)d_in[2];
    const float* b_ih0 = (const float*)d_in[3];
    const float* b_hh0 = (const float*)d_in[4];
    const float* W_ih1 = (const float*)d_in[5];
    const float* W_hh1 = (const float*)d_in[6];
    const float* b_ih1 = (const float*)d_in[7];
    const float* b_hh1 = (const float*)d_in[8];
    const float* W_out = (const float*)d_in[9];
    const float* b_out = (const float*)d_in[10];
    float* out = (float*)d_out;

    float *xp, *seq, *hbuf;
    cudaGetSymbolAddress((void**)&xp,   g_xp);
    cudaGetSymbolAddress((void**)&seq,  g_seq);
    cudaGetSymbolAddress((void**)&hbuf, g_h);
    float* hA = hbuf;
    float* hB = hbuf + B_ * H_;

    const int smem_bytes =
        (512 * 32 + NWRP * 16 * HSPW + 2 * NWRP * 512) * 4;  // 167936
    cudaFuncSetAttribute(rnn_layer_kernel,
                         cudaFuncAttributeMaxDynamicSharedMemorySize, smem_bytes);

    dim3 gg(B_ * S_ / 128, H_ / 64);  // (512, 8)
    dim3 gr(B_ / 16, H_ / 32);        // (8, 16) = 128 persistent blocks

    // layer 0
    sgemm_bias<<<gg, 256>>>(x, W_ih0, b_ih0, b_hh0, xp, B_ * S_, H_, IN_);
    rnn_layer_kernel<<<gr, 512, smem_bytes>>>(xp, W_hh0, hA, hB, seq);

    // layer 1
    sgemm_bias<<<gg, 256>>>(seq, W_ih1, b_ih1, b_hh1, xp, B_ * S_, H_, H_);
    rnn_layer_kernel<<<gr, 512, smem_bytes>>>(xp, W_hh1, hA, hB, nullptr);

    // output head on h_{S-1} (t=511 odd -> final state in hB)
    out_kernel<<<B_, 256>>>(hB, W_out, b_out, out);
}